// round 4
// baseline (speedup 1.0000x reference)
#include <cuda_runtime.h>
#include <math_constants.h>

#define BB 8
#define NN 2048
#define KNN 20
#define NTOT (BB*NN)
#define EPSB 1e-5f

// ---------------- scratch (device globals; no allocation allowed) ----------
__device__ int      g_idx[NTOT*KNN];
__device__ float    g_x1[NTOT*64];
__device__ float    g_x2[NTOT*64];
__device__ float    g_x3[NTOT*64];
__device__ float    g_Y[NTOT*64];
__device__ float    g_T[NTOT*64];

__device__ __forceinline__ float lrelu(float z){ return z >= 0.f ? z : 0.2f*z; }

// ---------------- kNN (verified): per-batch pts in smem, top-20 insertion --
__global__ __launch_bounds__(256) void knn_kernel(const float* __restrict__ x, int which)
{
    __shared__ float4 pts[NN];
    int b = blockIdx.x;
    const float* base;
    int stride;
    if (which == 0){ base = x    + (size_t)b*NN*3;        stride = 3;  }
    else if (which == 1){ base = g_x1 + (size_t)b*NN*64 + 6; stride = 64; }
    else {               base = g_x2 + (size_t)b*NN*64 + 6; stride = 64; }

    for (int j = threadIdx.x; j < NN; j += 256){
        float px = base[(size_t)j*stride + 0];
        float py = base[(size_t)j*stride + 1];
        float pz = base[(size_t)j*stride + 2];
        pts[j] = make_float4(px, py, pz, px*px + py*py + pz*pz);
    }
    __syncthreads();

    int i = blockIdx.y*256 + threadIdx.x;
    float4 q = pts[i];

    float bd[KNN]; int bi[KNN];
#pragma unroll
    for (int t = 0; t < KNN; t++){ bd[t] = -CUDART_INF_F; bi[t] = 0; }

#pragma unroll 4
    for (int j = 0; j < NN; j++){
        float4 p = pts[j];
        float nd = 2.f*(q.x*p.x + q.y*p.y + q.z*p.z) - q.w - p.w;
        if (nd > bd[KNN-1]){
            int t = KNN-1;
            while (t > 0 && bd[t-1] < nd){ bd[t] = bd[t-1]; bi[t] = bi[t-1]; t--; }
            bd[t] = nd; bi[t] = j;
        }
    }
    int* o = g_idx + ((size_t)b*NN + i)*KNN;
#pragma unroll
    for (int t = 0; t < KNN; t++) o[t] = bi[t];
}

// ---------------- gemmYT: Y' = s*(x@Wlo^T), T' = s*(x@Wd^T)+b --------------
template<int C, int SEL>
__global__ __launch_bounds__(256) void gemmYT_kernel(
    const float* __restrict__ x, const float* __restrict__ W,
    const float* __restrict__ bng, const float* __restrict__ bnb,
    const float* __restrict__ bnm, const float* __restrict__ bnv)
{
    const float* __restrict__ xin = (SEL == 0) ? x : (SEL == 1) ? g_x1 : g_x2;

    __shared__ __align__(16) float Wlo[C*64];
    __shared__ __align__(16) float Wd [C*64];
    __shared__ __align__(16) float xS [32*C];

    int tid = threadIdx.x;
    int pt0 = blockIdx.x*32;

    for (int t = tid; t < C*64; t += 256){
        int o = t & 63, c = t >> 6;
        float lo = W[(size_t)o*(2*C) + c];
        Wlo[c*64 + o] = lo;
        Wd [c*64 + o] = W[(size_t)o*(2*C) + C + c] - lo;
    }
    for (int t = tid; t < 32*C; t += 256){
        int p = t / C, c = t % C;
        xS[p*C + c] = xin[((size_t)pt0 + p)*C + c];
    }

    int o = tid & 63;
    float s = bng[o]*rsqrtf(bnv[o] + EPSB);
    float b = bnb[o] - bnm[o]*s;
    __syncthreads();

#pragma unroll
    for (int i = 0; i < 8; i++){
        int p = (tid >> 6) + 4*i;
        float accY = 0.f, accT = 0.f;
#pragma unroll 8
        for (int c = 0; c < C; c++){
            float xv = xS[p*C + c];
            accY = fmaf(xv, Wlo[c*64 + o], accY);
            accT = fmaf(xv, Wd [c*64 + o], accT);
        }
        g_Y[((size_t)pt0 + p)*64 + o] = s*accY;
        g_T[((size_t)pt0 + p)*64 + o] = s*accT + b;
    }
}

// ---------------- edge_conv2: h1=lrelu(Y'[j]+T'[i]) tile -> conv-b -> k-max -
template<int SEL_OUT>
__global__ __launch_bounds__(512) void edge_conv2_kernel(
    const float* __restrict__ Wb,
    const float* __restrict__ bng, const float* __restrict__ bnb,
    const float* __restrict__ bnm, const float* __restrict__ bnv)
{
    float* __restrict__ xout = (SEL_OUT == 1) ? g_x1 : g_x2;

    __shared__ __align__(16) float Ws[64*64];
    __shared__ __align__(16) float As[64*161];
    __shared__ __align__(16) float red[4*8*64];
    __shared__ int idxS[160];

    int tid = threadIdx.x;
    int pt0 = blockIdx.x*8;

    for (int t = tid; t < 4096; t += 512){
        int o = t & 63, c = t >> 6;
        Ws[c*64 + o] = Wb[(size_t)o*64 + c];
    }
    if (tid < 160) idxS[tid] = g_idx[(size_t)pt0*KNN + tid];
    __syncthreads();

    for (int e = tid; e < 160*64; e += 512){
        int r = e >> 6, c = e & 63;
        int p = r / KNN;
        int bb = (pt0 + p) >> 11;
        int j = idxS[r];
        float v = g_Y[((size_t)bb*NN + j)*64 + c] + g_T[((size_t)pt0 + p)*64 + c];
        As[c*161 + r] = lrelu(v);
    }

    int r5 = tid & 31;
    int tn = tid >> 5;
    int o0 = tn*4;

    float s2[4], b2[4];
#pragma unroll
    for (int q = 0; q < 4; q++){
        int o = o0 + q;
        float r = rsqrtf(bnv[o] + EPSB);
        s2[q] = bng[o]*r; b2[q] = bnb[o] - bnm[o]*s2[q];
    }
    __syncthreads();

    float acc[5][4];
#pragma unroll
    for (int i = 0; i < 5; i++)
#pragma unroll
        for (int q = 0; q < 4; q++) acc[i][q] = 0.f;

#pragma unroll 4
    for (int c = 0; c < 64; c++){
        float4 w = *(const float4*)&Ws[c*64 + o0];
        float a0 = As[c*161 + r5*5 + 0];
        float a1 = As[c*161 + r5*5 + 1];
        float a2 = As[c*161 + r5*5 + 2];
        float a3 = As[c*161 + r5*5 + 3];
        float a4 = As[c*161 + r5*5 + 4];
        acc[0][0]=fmaf(a0,w.x,acc[0][0]); acc[0][1]=fmaf(a0,w.y,acc[0][1]);
        acc[0][2]=fmaf(a0,w.z,acc[0][2]); acc[0][3]=fmaf(a0,w.w,acc[0][3]);
        acc[1][0]=fmaf(a1,w.x,acc[1][0]); acc[1][1]=fmaf(a1,w.y,acc[1][1]);
        acc[1][2]=fmaf(a1,w.z,acc[1][2]); acc[1][3]=fmaf(a1,w.w,acc[1][3]);
        acc[2][0]=fmaf(a2,w.x,acc[2][0]); acc[2][1]=fmaf(a2,w.y,acc[2][1]);
        acc[2][2]=fmaf(a2,w.z,acc[2][2]); acc[2][3]=fmaf(a2,w.w,acc[2][3]);
        acc[3][0]=fmaf(a3,w.x,acc[3][0]); acc[3][1]=fmaf(a3,w.y,acc[3][1]);
        acc[3][2]=fmaf(a3,w.z,acc[3][2]); acc[3][3]=fmaf(a3,w.w,acc[3][3]);
        acc[4][0]=fmaf(a4,w.x,acc[4][0]); acc[4][1]=fmaf(a4,w.y,acc[4][1]);
        acc[4][2]=fmaf(a4,w.z,acc[4][2]); acc[4][3]=fmaf(a4,w.w,acc[4][3]);
    }

    int p    = r5 >> 2;
    int part = r5 & 3;
#pragma unroll
    for (int q = 0; q < 4; q++){
        float mx = -CUDART_INF_F;
#pragma unroll
        for (int i = 0; i < 5; i++)
            mx = fmaxf(mx, lrelu(fmaf(acc[i][q], s2[q], b2[q])));
        red[(part*8 + p)*64 + o0 + q] = mx;
    }
    __syncthreads();

    {
        int pp = tid >> 6, oo = tid & 63;
        float m = red[(0*8 + pp)*64 + oo];
        m = fmaxf(m, red[(1*8 + pp)*64 + oo]);
        m = fmaxf(m, red[(2*8 + pp)*64 + oo]);
        m = fmaxf(m, red[(3*8 + pp)*64 + oo]);
        xout[((size_t)pt0 + pp)*64 + oo] = m;
    }
}

// ---------------- edge_max (stage 3): x3 = max_k lrelu(Y'[j]+T'[i]) --------
__global__ __launch_bounds__(256) void edge_max_kernel()
{
    __shared__ int idxS[4*KNN];
    int tid = threadIdx.x;
    int pt0 = blockIdx.x*4;
    if (tid < 4*KNN) idxS[tid] = g_idx[(size_t)pt0*KNN + tid];
    __syncthreads();

    int p = tid >> 6, o = tid & 63;
    int pt = pt0 + p;
    int bb = pt >> 11;
    float tv = g_T[(size_t)pt*64 + o];
    float m = -CUDART_INF_F;
#pragma unroll
    for (int k = 0; k < KNN; k++){
        int j = idxS[p*KNN + k];
        m = fmaxf(m, lrelu(g_Y[((size_t)bb*NN + j)*64 + o] + tv));
    }
    g_x3[(size_t)pt*64 + o] = m;
}

// ---------------- final: per-(batch, n-tile) block streams all m ----------
// grid (1024/64, BB) = (16, 8); block 256; 4x4 micro-tile; running max over m.
// Writes feat directly: out[bb*1024 + n0 + o].
__global__ __launch_bounds__(256) void final_kernel(
    const float* __restrict__ W6,
    const float* __restrict__ bn6g, const float* __restrict__ bn6b,
    const float* __restrict__ bn6m, const float* __restrict__ bn6v,
    float* __restrict__ outfeat)
{
    __shared__ float As[64*68];
    __shared__ float Bs[64*68];
    __shared__ float ss6[64], sb6[64];
    __shared__ float red[64*16];

    int tid = threadIdx.x;
    int n0 = blockIdx.x*64;
    int bb = blockIdx.y;

    if (tid < 64){
        int o = n0 + tid;
        float r = rsqrtf(bn6v[o] + EPSB);
        ss6[tid] = bn6g[o]*r; sb6[tid] = bn6b[o] - bn6m[o]*ss6[tid];
    }
    __syncthreads();

    int tm = tid & 15, tn = tid >> 4;
    float s6[4], b6[4];
#pragma unroll
    for (int q = 0; q < 4; q++){ s6[q] = ss6[tn*4+q]; b6[q] = sb6[tn*4+q]; }

    float vmax[4] = {-CUDART_INF_F, -CUDART_INF_F, -CUDART_INF_F, -CUDART_INF_F};

    for (int mi = 0; mi < 32; mi++){
        size_t m1 = (size_t)bb*NN + mi*64;
        float acc[4][4];
#pragma unroll
        for (int i = 0; i < 4; i++)
#pragma unroll
            for (int j = 0; j < 4; j++) acc[i][j] = 0.f;

        for (int ch = 0; ch < 3; ch++){
            const float* src = (ch == 0) ? g_x1 : (ch == 1) ? g_x2 : g_x3;
            __syncthreads();
            for (int t = tid; t < 4096; t += 256){
                int m = t >> 6, c = t & 63;
                As[c*68 + m] = src[(m1 + m)*64 + c];
            }
            for (int t = tid; t < 4096; t += 256){
                int nn = t >> 6, c = t & 63;
                Bs[c*68 + nn] = W6[(size_t)(n0+nn)*192 + ch*64 + c];
            }
            __syncthreads();
#pragma unroll 8
            for (int c = 0; c < 64; c++){
                float4 a  = *(const float4*)&As[c*68 + tm*4];
                float4 bv = *(const float4*)&Bs[c*68 + tn*4];
                acc[0][0] = fmaf(a.x,bv.x,acc[0][0]); acc[0][1] = fmaf(a.x,bv.y,acc[0][1]);
                acc[0][2] = fmaf(a.x,bv.z,acc[0][2]); acc[0][3] = fmaf(a.x,bv.w,acc[0][3]);
                acc[1][0] = fmaf(a.y,bv.x,acc[1][0]); acc[1][1] = fmaf(a.y,bv.y,acc[1][1]);
                acc[1][2] = fmaf(a.y,bv.z,acc[1][2]); acc[1][3] = fmaf(a.y,bv.w,acc[1][3]);
                acc[2][0] = fmaf(a.z,bv.x,acc[2][0]); acc[2][1] = fmaf(a.z,bv.y,acc[2][1]);
                acc[2][2] = fmaf(a.z,bv.z,acc[2][2]); acc[2][3] = fmaf(a.z,bv.w,acc[2][3]);
                acc[3][0] = fmaf(a.w,bv.x,acc[3][0]); acc[3][1] = fmaf(a.w,bv.y,acc[3][1]);
                acc[3][2] = fmaf(a.w,bv.z,acc[3][2]); acc[3][3] = fmaf(a.w,bv.w,acc[3][3]);
            }
        }
#pragma unroll
        for (int nq = 0; nq < 4; nq++){
#pragma unroll
            for (int mq = 0; mq < 4; mq++)
                vmax[nq] = fmaxf(vmax[nq], lrelu(fmaf(acc[mq][nq], s6[nq], b6[nq])));
        }
    }

    __syncthreads();
#pragma unroll
    for (int nq = 0; nq < 4; nq++) red[(tn*4+nq)*16 + tm] = vmax[nq];
    __syncthreads();
    if (tid < 64){
        float mx = -CUDART_INF_F;
#pragma unroll
        for (int t = 0; t < 16; t++) mx = fmaxf(mx, red[tid*16 + t]);
        outfeat[(size_t)bb*1024 + n0 + tid] = mx;
    }
}

// ---------------- x4^T via smem transpose ----------------------------------
// grid (32 n-tiles, BB, 3 src); out[8192 + b*192*2048 + c*2048 + n]
__global__ __launch_bounds__(256) void x4t_kernel(float* __restrict__ out)
{
    __shared__ float T[64*65];
    int tid = threadIdx.x;
    int n0 = blockIdx.x*64;
    int bb = blockIdx.y;
    int ch = blockIdx.z;
    const float* src = (ch == 0) ? g_x1 : (ch == 1) ? g_x2 : g_x3;

    for (int t = tid; t < 4096; t += 256){
        int c = t & 63, n = t >> 6;
        T[c*65 + n] = src[((size_t)bb*NN + n0 + n)*64 + c];
    }
    __syncthreads();
    size_t base = (size_t)BB*1024 + (size_t)bb*192*NN + (size_t)ch*64*NN;
    for (int t = tid; t < 4096; t += 256){
        int n = t & 63, c = t >> 6;
        out[base + (size_t)c*NN + n0 + n] = T[c*65 + n];
    }
}

// ---------------- launch ----------------------------------------------------
extern "C" void kernel_launch(void* const* d_in, const int* in_sizes, int n_in,
                              void* d_out, int out_size)
{
    const float* x    = (const float*)d_in[0];
    const float* W1   = (const float*)d_in[1];
    const float* W2   = (const float*)d_in[2];
    const float* W3   = (const float*)d_in[3];
    const float* W4   = (const float*)d_in[4];
    const float* W5   = (const float*)d_in[5];
    const float* W6   = (const float*)d_in[6];
    const float* bng  = (const float*)d_in[7];
    const float* bnb  = (const float*)d_in[8];
    const float* bnm  = (const float*)d_in[9];
    const float* bnv  = (const float*)d_in[10];
    const float* bn6g = (const float*)d_in[11];
    const float* bn6b = (const float*)d_in[12];
    const float* bn6m = (const float*)d_in[13];
    const float* bn6v = (const float*)d_in[14];
    float* out = (float*)d_out;

    // idx 0-2: stage 1
    knn_kernel<<<dim3(BB, NN/256), 256>>>(x, 0);
    gemmYT_kernel<3,0><<<NTOT/32, 256>>>(x, W1, bng, bnb, bnm, bnv);
    edge_conv2_kernel<1><<<NTOT/8, 512>>>(W2, bng+64, bnb+64, bnm+64, bnv+64);

    // idx 3: PROBE — ncu captures our launch #3. Reads g_x1 (ready) and
    // stale g_x2/g_x3; its output region is fully overwritten by the real
    // final_kernel below, so the final d_out is deterministic and correct.
    final_kernel<<<dim3(1024/64, BB), 256>>>(W6, bn6g, bn6b, bn6m, bn6v, out);

    // stage 2
    knn_kernel<<<dim3(BB, NN/256), 256>>>(x, 1);
    gemmYT_kernel<64,1><<<NTOT/32, 256>>>(x, W3, bng+2*64, bnb+2*64, bnm+2*64, bnv+2*64);
    edge_conv2_kernel<2><<<NTOT/8, 512>>>(W4, bng+3*64, bnb+3*64, bnm+3*64, bnv+3*64);

    // stage 3
    knn_kernel<<<dim3(BB, NN/256), 256>>>(x, 2);
    gemmYT_kernel<64,2><<<NTOT/32, 256>>>(x, W5, bng+4*64, bnb+4*64, bnm+4*64, bnv+4*64);
    edge_max_kernel<<<NTOT/4, 256>>>();

    // final block + global max pool (writes feat), then x4^T
    final_kernel<<<dim3(1024/64, BB), 256>>>(W6, bn6g, bn6b, bn6m, bn6v, out);
    x4t_kernel<<<dim3(NN/64, BB, 3), 256>>>(out);
}

// round 5
// speedup vs baseline: 6.7637x; 6.7637x over previous
#include <cuda_runtime.h>
#include <math_constants.h>

#define BB 8
#define NN 2048
#define KNN 20
#define NTOT (BB*NN)
#define EPSB 1e-5f

// ---------------- scratch (device globals; no allocation allowed) ----------
__device__ int      g_idx[NTOT*KNN];
__device__ float    g_x1[NTOT*64];
__device__ float    g_x2[NTOT*64];
__device__ float    g_x3[NTOT*64];
__device__ float    g_Y[NTOT*64];
__device__ float    g_T[NTOT*64];
__device__ unsigned g_gmax[BB*1024];

__device__ __forceinline__ float lrelu(float z){ return z >= 0.f ? z : 0.2f*z; }
__device__ __forceinline__ unsigned fenc(float f){
    unsigned u = __float_as_uint(f);
    return (u & 0x80000000u) ? ~u : (u | 0x80000000u);
}
__device__ __forceinline__ float fdec(unsigned e){
    return (e & 0x80000000u) ? __uint_as_float(e ^ 0x80000000u) : __uint_as_float(~e);
}

// ---------------- kNN v2: register-only branchless top-20 ------------------
__global__ __launch_bounds__(256) void knn_kernel(const float* __restrict__ x, int which)
{
    __shared__ float4 pts[NN];
    int b = blockIdx.x;
    const float* base;
    int stride;
    if (which == 0){ base = x    + (size_t)b*NN*3;        stride = 3;  }
    else if (which == 1){ base = g_x1 + (size_t)b*NN*64 + 6; stride = 64; }
    else {               base = g_x2 + (size_t)b*NN*64 + 6; stride = 64; }

    for (int j = threadIdx.x; j < NN; j += 256){
        float px = base[(size_t)j*stride + 0];
        float py = base[(size_t)j*stride + 1];
        float pz = base[(size_t)j*stride + 2];
        pts[j] = make_float4(px, py, pz, px*px + py*py + pz*pz);
    }
    __syncthreads();

    int i = blockIdx.y*256 + threadIdx.x;
    float4 q = pts[i];

    float bd[KNN]; int bi[KNN];
#pragma unroll
    for (int t = 0; t < KNN; t++){ bd[t] = -CUDART_INF_F; bi[t] = 0; }

    for (int j = 0; j < NN; j++){
        float4 p = pts[j];
        float nd = 2.f*(q.x*p.x + q.y*p.y + q.z*p.z) - q.w - p.w;
        if (nd > bd[KNN-1]){
            // branchless insert: bubble candidate down, static indices only
            float cd = nd; int ci = j;
#pragma unroll
            for (int t = 0; t < KNN; t++){
                bool sw = cd > bd[t];
                float td = bd[t]; int ti = bi[t];
                bd[t] = sw ? cd : td;  bi[t] = sw ? ci : ti;
                cd    = sw ? td : cd;  ci    = sw ? ti : ci;
            }
        }
    }
    int* o = g_idx + ((size_t)b*NN + i)*KNN;
#pragma unroll
    for (int t = 0; t < KNN; t++) o[t] = bi[t];
}

// ---------------- gemmYT: Y' = s*(x@Wlo^T), T' = s*(x@Wd^T)+b --------------
template<int C, int SEL>
__global__ __launch_bounds__(256) void gemmYT_kernel(
    const float* __restrict__ x, const float* __restrict__ W,
    const float* __restrict__ bng, const float* __restrict__ bnb,
    const float* __restrict__ bnm, const float* __restrict__ bnv)
{
    const float* __restrict__ xin = (SEL == 0) ? x : (SEL == 1) ? g_x1 : g_x2;

    __shared__ __align__(16) float Wlo[C*64];
    __shared__ __align__(16) float Wd [C*64];
    __shared__ __align__(16) float xS [32*C];

    int tid = threadIdx.x;
    int pt0 = blockIdx.x*32;

    for (int t = tid; t < C*64; t += 256){
        int o = t & 63, c = t >> 6;
        float lo = W[(size_t)o*(2*C) + c];
        Wlo[c*64 + o] = lo;
        Wd [c*64 + o] = W[(size_t)o*(2*C) + C + c] - lo;
    }
    for (int t = tid; t < 32*C; t += 256){
        int p = t / C, c = t % C;
        xS[p*C + c] = xin[((size_t)pt0 + p)*C + c];
    }

    int o = tid & 63;
    float s = bng[o]*rsqrtf(bnv[o] + EPSB);
    float b = bnb[o] - bnm[o]*s;
    __syncthreads();

#pragma unroll
    for (int i = 0; i < 8; i++){
        int p = (tid >> 6) + 4*i;
        float accY = 0.f, accT = 0.f;
#pragma unroll 8
        for (int c = 0; c < C; c++){
            float xv = xS[p*C + c];
            accY = fmaf(xv, Wlo[c*64 + o], accY);
            accT = fmaf(xv, Wd [c*64 + o], accT);
        }
        g_Y[((size_t)pt0 + p)*64 + o] = s*accY;
        g_T[((size_t)pt0 + p)*64 + o] = s*accT + b;
    }
}

// ---------------- edge_conv2: h1=lrelu(Y'[j]+T'[i]) tile -> conv-b -> k-max -
template<int SEL_OUT>
__global__ __launch_bounds__(512) void edge_conv2_kernel(
    const float* __restrict__ Wb,
    const float* __restrict__ bng, const float* __restrict__ bnb,
    const float* __restrict__ bnm, const float* __restrict__ bnv)
{
    float* __restrict__ xout = (SEL_OUT == 1) ? g_x1 : g_x2;

    __shared__ __align__(16) float Ws[64*64];
    __shared__ __align__(16) float As[64*161];
    __shared__ __align__(16) float red[4*8*64];
    __shared__ int idxS[160];

    int tid = threadIdx.x;
    int pt0 = blockIdx.x*8;

    for (int t = tid; t < 4096; t += 512){
        int o = t & 63, c = t >> 6;
        Ws[c*64 + o] = Wb[(size_t)o*64 + c];
    }
    if (tid < 160) idxS[tid] = g_idx[(size_t)pt0*KNN + tid];
    __syncthreads();

    for (int e = tid; e < 160*64; e += 512){
        int r = e >> 6, c = e & 63;
        int p = r / KNN;
        int bb = (pt0 + p) >> 11;
        int j = idxS[r];
        float v = g_Y[((size_t)bb*NN + j)*64 + c] + g_T[((size_t)pt0 + p)*64 + c];
        As[c*161 + r] = lrelu(v);
    }

    int r5 = tid & 31;
    int tn = tid >> 5;
    int o0 = tn*4;

    float s2[4], b2[4];
#pragma unroll
    for (int q = 0; q < 4; q++){
        int o = o0 + q;
        float r = rsqrtf(bnv[o] + EPSB);
        s2[q] = bng[o]*r; b2[q] = bnb[o] - bnm[o]*s2[q];
    }
    __syncthreads();

    float acc[5][4];
#pragma unroll
    for (int i = 0; i < 5; i++)
#pragma unroll
        for (int q = 0; q < 4; q++) acc[i][q] = 0.f;

#pragma unroll 4
    for (int c = 0; c < 64; c++){
        float4 w = *(const float4*)&Ws[c*64 + o0];
        float a0 = As[c*161 + r5*5 + 0];
        float a1 = As[c*161 + r5*5 + 1];
        float a2 = As[c*161 + r5*5 + 2];
        float a3 = As[c*161 + r5*5 + 3];
        float a4 = As[c*161 + r5*5 + 4];
        acc[0][0]=fmaf(a0,w.x,acc[0][0]); acc[0][1]=fmaf(a0,w.y,acc[0][1]);
        acc[0][2]=fmaf(a0,w.z,acc[0][2]); acc[0][3]=fmaf(a0,w.w,acc[0][3]);
        acc[1][0]=fmaf(a1,w.x,acc[1][0]); acc[1][1]=fmaf(a1,w.y,acc[1][1]);
        acc[1][2]=fmaf(a1,w.z,acc[1][2]); acc[1][3]=fmaf(a1,w.w,acc[1][3]);
        acc[2][0]=fmaf(a2,w.x,acc[2][0]); acc[2][1]=fmaf(a2,w.y,acc[2][1]);
        acc[2][2]=fmaf(a2,w.z,acc[2][2]); acc[2][3]=fmaf(a2,w.w,acc[2][3]);
        acc[3][0]=fmaf(a3,w.x,acc[3][0]); acc[3][1]=fmaf(a3,w.y,acc[3][1]);
        acc[3][2]=fmaf(a3,w.z,acc[3][2]); acc[3][3]=fmaf(a3,w.w,acc[3][3]);
        acc[4][0]=fmaf(a4,w.x,acc[4][0]); acc[4][1]=fmaf(a4,w.y,acc[4][1]);
        acc[4][2]=fmaf(a4,w.z,acc[4][2]); acc[4][3]=fmaf(a4,w.w,acc[4][3]);
    }

    int p    = r5 >> 2;
    int part = r5 & 3;
#pragma unroll
    for (int q = 0; q < 4; q++){
        float mx = -CUDART_INF_F;
#pragma unroll
        for (int i = 0; i < 5; i++)
            mx = fmaxf(mx, lrelu(fmaf(acc[i][q], s2[q], b2[q])));
        red[(part*8 + p)*64 + o0 + q] = mx;
    }
    __syncthreads();

    {
        int pp = tid >> 6, oo = tid & 63;
        float m = red[(0*8 + pp)*64 + oo];
        m = fmaxf(m, red[(1*8 + pp)*64 + oo]);
        m = fmaxf(m, red[(2*8 + pp)*64 + oo]);
        m = fmaxf(m, red[(3*8 + pp)*64 + oo]);
        xout[((size_t)pt0 + pp)*64 + oo] = m;
    }
}

// ---------------- edge_max (stage 3): x3 = max_k lrelu(Y'[j]+T'[i]) --------
__global__ __launch_bounds__(256) void edge_max_kernel()
{
    __shared__ int idxS[4*KNN];
    int tid = threadIdx.x;
    int pt0 = blockIdx.x*4;
    if (tid < 4*KNN) idxS[tid] = g_idx[(size_t)pt0*KNN + tid];
    __syncthreads();

    int p = tid >> 6, o = tid & 63;
    int pt = pt0 + p;
    int bb = pt >> 11;
    float tv = g_T[(size_t)pt*64 + o];
    float m = -CUDART_INF_F;
#pragma unroll
    for (int k = 0; k < KNN; k++){
        int j = idxS[p*KNN + k];
        m = fmaxf(m, lrelu(g_Y[((size_t)bb*NN + j)*64 + o] + tv));
    }
    g_x3[(size_t)pt*64 + o] = m;
}

// ---------------- init / final GEMM v2 / outputs ---------------------------
__global__ void init_gmax_kernel(){
    int t = blockIdx.x*256 + threadIdx.x;
    if (t < BB*1024) g_gmax[t] = 0u;
}

// grid (16 n-tiles, BB, 4 m-chunks), 256 thr. Bs loaded ONCE (all 192 c).
// Dynamic smem: Bs[192*68] then As[192*68].
__global__ __launch_bounds__(256) void final_kernel(
    const float* __restrict__ W6,
    const float* __restrict__ bn6g, const float* __restrict__ bn6b,
    const float* __restrict__ bn6m, const float* __restrict__ bn6v)
{
    extern __shared__ float dsm[];
    float* Bs = dsm;              // [192*68]
    float* As = dsm + 192*68;     // [192*68]
    __shared__ float ss6[64], sb6[64];
    __shared__ float red[64*16];

    int tid = threadIdx.x;
    int n0 = blockIdx.x*64;
    int bb = blockIdx.y;
    int mc = blockIdx.z;

    if (tid < 64){
        int o = n0 + tid;
        float r = rsqrtf(bn6v[o] + EPSB);
        ss6[tid] = bn6g[o]*r; sb6[tid] = bn6b[o] - bn6m[o]*ss6[tid];
    }

    // load all of W6 tile once: Bs[(ch*64+c)*68 + nn]
    for (int ch = 0; ch < 3; ch++)
        for (int t = tid; t < 4096; t += 256){
            int nn = t >> 6, c = t & 63;
            Bs[(ch*64 + c)*68 + nn] = W6[(size_t)(n0+nn)*192 + ch*64 + c];
        }
    __syncthreads();

    int tm = tid & 15, tn = tid >> 4;
    float s6[4], b6[4];
#pragma unroll
    for (int q = 0; q < 4; q++){ s6[q] = ss6[tn*4+q]; b6[q] = sb6[tn*4+q]; }

    float vmax[4] = {-CUDART_INF_F, -CUDART_INF_F, -CUDART_INF_F, -CUDART_INF_F};

    for (int mi = mc*8; mi < mc*8 + 8; mi++){
        size_t m1 = (size_t)bb*NN + mi*64;
        __syncthreads();
        {
            const float* s1 = g_x1; const float* s2 = g_x2; const float* s3 = g_x3;
            for (int t = tid; t < 4096; t += 256){
                int m = t >> 6, c = t & 63;
                As[(0*64 + c)*68 + m] = s1[(m1 + m)*64 + c];
            }
            for (int t = tid; t < 4096; t += 256){
                int m = t >> 6, c = t & 63;
                As[(1*64 + c)*68 + m] = s2[(m1 + m)*64 + c];
            }
            for (int t = tid; t < 4096; t += 256){
                int m = t >> 6, c = t & 63;
                As[(2*64 + c)*68 + m] = s3[(m1 + m)*64 + c];
            }
        }
        __syncthreads();

        float acc[4][4];
#pragma unroll
        for (int i = 0; i < 4; i++)
#pragma unroll
            for (int j = 0; j < 4; j++) acc[i][j] = 0.f;

#pragma unroll 8
        for (int c = 0; c < 192; c++){
            float4 a  = *(const float4*)&As[c*68 + tm*4];
            float4 bv = *(const float4*)&Bs[c*68 + tn*4];
            acc[0][0] = fmaf(a.x,bv.x,acc[0][0]); acc[0][1] = fmaf(a.x,bv.y,acc[0][1]);
            acc[0][2] = fmaf(a.x,bv.z,acc[0][2]); acc[0][3] = fmaf(a.x,bv.w,acc[0][3]);
            acc[1][0] = fmaf(a.y,bv.x,acc[1][0]); acc[1][1] = fmaf(a.y,bv.y,acc[1][1]);
            acc[1][2] = fmaf(a.y,bv.z,acc[1][2]); acc[1][3] = fmaf(a.y,bv.w,acc[1][3]);
            acc[2][0] = fmaf(a.z,bv.x,acc[2][0]); acc[2][1] = fmaf(a.z,bv.y,acc[2][1]);
            acc[2][2] = fmaf(a.z,bv.z,acc[2][2]); acc[2][3] = fmaf(a.z,bv.w,acc[2][3]);
            acc[3][0] = fmaf(a.w,bv.x,acc[3][0]); acc[3][1] = fmaf(a.w,bv.y,acc[3][1]);
            acc[3][2] = fmaf(a.w,bv.z,acc[3][2]); acc[3][3] = fmaf(a.w,bv.w,acc[3][3]);
        }
#pragma unroll
        for (int nq = 0; nq < 4; nq++)
#pragma unroll
            for (int mq = 0; mq < 4; mq++)
                vmax[nq] = fmaxf(vmax[nq], lrelu(fmaf(acc[mq][nq], s6[nq], b6[nq])));
    }

    __syncthreads();
#pragma unroll
    for (int nq = 0; nq < 4; nq++) red[(tn*4+nq)*16 + tm] = vmax[nq];
    __syncthreads();
    if (tid < 64){
        float mx = -CUDART_INF_F;
#pragma unroll
        for (int t = 0; t < 16; t++) mx = fmaxf(mx, red[tid*16 + t]);
        atomicMax(&g_gmax[bb*1024 + n0 + tid], fenc(mx));
    }
}

__global__ void feat_kernel(float* __restrict__ out){
    int t = blockIdx.x*256 + threadIdx.x;
    if (t < BB*1024) out[t] = fdec(g_gmax[t]);
}

// ---------------- x4^T via smem transpose ----------------------------------
__global__ __launch_bounds__(256) void x4t_kernel(float* __restrict__ out)
{
    __shared__ float T[64*65];
    int tid = threadIdx.x;
    int n0 = blockIdx.x*64;
    int bb = blockIdx.y;
    int ch = blockIdx.z;
    const float* src = (ch == 0) ? g_x1 : (ch == 1) ? g_x2 : g_x3;

    for (int t = tid; t < 4096; t += 256){
        int c = t & 63, n = t >> 6;
        T[c*65 + n] = src[((size_t)bb*NN + n0 + n)*64 + c];
    }
    __syncthreads();
    size_t base = (size_t)BB*1024 + (size_t)bb*192*NN + (size_t)ch*64*NN;
    for (int t = tid; t < 4096; t += 256){
        int n = t & 63, c = t >> 6;
        out[base + (size_t)c*NN + n0 + n] = T[c*65 + n];
    }
}

// ---------------- launch ----------------------------------------------------
extern "C" void kernel_launch(void* const* d_in, const int* in_sizes, int n_in,
                              void* d_out, int out_size)
{
    const float* x    = (const float*)d_in[0];
    const float* W1   = (const float*)d_in[1];
    const float* W2   = (const float*)d_in[2];
    const float* W3   = (const float*)d_in[3];
    const float* W4   = (const float*)d_in[4];
    const float* W5   = (const float*)d_in[5];
    const float* W6   = (const float*)d_in[6];
    const float* bng  = (const float*)d_in[7];
    const float* bnb  = (const float*)d_in[8];
    const float* bnm  = (const float*)d_in[9];
    const float* bnv  = (const float*)d_in[10];
    const float* bn6g = (const float*)d_in[11];
    const float* bn6b = (const float*)d_in[12];
    const float* bn6m = (const float*)d_in[13];
    const float* bn6v = (const float*)d_in[14];
    float* out = (float*)d_out;

    static int smem_set = 0;
    if (!smem_set){
        cudaFuncSetAttribute(final_kernel,
            cudaFuncAttributeMaxDynamicSharedMemorySize, 2*192*68*4);
        smem_set = 1;
    }
    const int FSMEM = 2*192*68*4;

    // Stage 1                      (launch idx)
    knn_kernel<<<dim3(BB, NN/256), 256>>>(x, 0);                              // 0
    gemmYT_kernel<3,0><<<NTOT/32, 256>>>(x, W1, bng, bnb, bnm, bnv);          // 1
    edge_conv2_kernel<1><<<NTOT/8, 512>>>(W2, bng+64, bnb+64, bnm+64, bnv+64);// 2

    // Stage 2 (gemmYT moved before knn1 — only needs g_x1; idx 3 = ncu target)
    gemmYT_kernel<64,1><<<NTOT/32, 256>>>(x, W3, bng+2*64, bnb+2*64, bnm+2*64, bnv+2*64); // 3
    gemmYT_kernel<64,1><<<NTOT/32, 256>>>(x, W3, bng+2*64, bnb+2*64, bnm+2*64, bnv+2*64); // 4 dup (idempotent probe)
    knn_kernel<<<dim3(BB, NN/256), 256>>>(x, 1);                              // 5
    knn_kernel<<<dim3(BB, NN/256), 256>>>(x, 1);                              // 6 dup
    edge_conv2_kernel<2><<<NTOT/8, 512>>>(W4, bng+3*64, bnb+3*64, bnm+3*64, bnv+3*64); // 7

    // Stage 3
    gemmYT_kernel<64,2><<<NTOT/32, 256>>>(x, W5, bng+4*64, bnb+4*64, bnm+4*64, bnv+4*64); // 8
    gemmYT_kernel<64,2><<<NTOT/32, 256>>>(x, W5, bng+4*64, bnb+4*64, bnm+4*64, bnv+4*64); // 9 dup
    knn_kernel<<<dim3(BB, NN/256), 256>>>(x, 2);                              // 10
    knn_kernel<<<dim3(BB, NN/256), 256>>>(x, 2);                              // 11 dup
    edge_max_kernel<<<NTOT/4, 256>>>();                                       // 12
    edge_max_kernel<<<NTOT/4, 256>>>();                                       // 13 dup

    // Final block + global max pool
    init_gmax_kernel<<<32, 256>>>();
    final_kernel<<<dim3(1024/64, BB, 4), 256, FSMEM>>>(W6, bn6g, bn6b, bn6m, bn6v);
    feat_kernel<<<32, 256>>>(out);
    x4t_kernel<<<dim3(NN/64, BB, 3), 256>>>(out);
}

// round 6
// speedup vs baseline: 10.0815x; 1.4905x over previous
#include <cuda_runtime.h>
#include <math_constants.h>

#define BB 8
#define NN 2048
#define KNN 20
#define NTOT (BB*NN)
#define EPSB 1e-5f

// ---------------- scratch (device globals; no allocation allowed) ----------
__device__ int      g_idx[NTOT*KNN];
__device__ float    g_x1[NTOT*64];
__device__ float    g_x2[NTOT*64];
__device__ float    g_x3[NTOT*64];
__device__ float    g_Y[NTOT*64];
__device__ float    g_T[NTOT*64];
__device__ unsigned g_gmax[BB*1024];

__device__ __forceinline__ float lrelu(float z){ return z >= 0.f ? z : 0.2f*z; }
__device__ __forceinline__ unsigned fenc(float f){
    unsigned u = __float_as_uint(f);
    return (u & 0x80000000u) ? ~u : (u | 0x80000000u);
}
__device__ __forceinline__ float fdec(unsigned e){
    return (e & 0x80000000u) ? __uint_as_float(e ^ 0x80000000u) : __uint_as_float(~e);
}

// ---------------- kNN: register-only branchless top-20 ---------------------
__global__ __launch_bounds__(256) void knn_kernel(const float* __restrict__ x, int which)
{
    __shared__ float4 pts[NN];
    int b = blockIdx.x;
    const float* base;
    int stride;
    if (which == 0){ base = x    + (size_t)b*NN*3;        stride = 3;  }
    else if (which == 1){ base = g_x1 + (size_t)b*NN*64 + 6; stride = 64; }
    else {               base = g_x2 + (size_t)b*NN*64 + 6; stride = 64; }

    for (int j = threadIdx.x; j < NN; j += 256){
        float px = base[(size_t)j*stride + 0];
        float py = base[(size_t)j*stride + 1];
        float pz = base[(size_t)j*stride + 2];
        pts[j] = make_float4(px, py, pz, px*px + py*py + pz*pz);
    }
    __syncthreads();

    int i = blockIdx.y*256 + threadIdx.x;
    float4 q = pts[i];

    float bd[KNN]; int bi[KNN];
#pragma unroll
    for (int t = 0; t < KNN; t++){ bd[t] = -CUDART_INF_F; bi[t] = 0; }

    for (int j = 0; j < NN; j++){
        float4 p = pts[j];
        float nd = 2.f*(q.x*p.x + q.y*p.y + q.z*p.z) - q.w - p.w;
        if (nd > bd[KNN-1]){
            float cd = nd; int ci = j;
#pragma unroll
            for (int t = 0; t < KNN; t++){
                bool sw = cd > bd[t];
                float td = bd[t]; int ti = bi[t];
                bd[t] = sw ? cd : td;  bi[t] = sw ? ci : ti;
                cd    = sw ? td : cd;  ci    = sw ? ti : ci;
            }
        }
    }
    int* o = g_idx + ((size_t)b*NN + i)*KNN;
#pragma unroll
    for (int t = 0; t < KNN; t++) o[t] = bi[t];
}

// ---------------- gemmYT v2: Y' = s*(x@Wlo^T), T' = s*(x@Wd^T)+b -----------
// thread = (og = tid&15 -> 4 outputs, pq = tid>>4 -> 2 points). 16 FMA / 4 LDS.
template<int C, int SEL>
__global__ __launch_bounds__(256) void gemmYT_kernel(
    const float* __restrict__ x, const float* __restrict__ W,
    const float* __restrict__ bng, const float* __restrict__ bnb,
    const float* __restrict__ bnm, const float* __restrict__ bnv)
{
    const float* __restrict__ xin = (SEL == 0) ? x : (SEL == 1) ? g_x1 : g_x2;

    __shared__ __align__(16) float Wlo[C*64];
    __shared__ __align__(16) float Wd [C*64];
    __shared__ __align__(16) float xS [32*C];

    int tid = threadIdx.x;
    int pt0 = blockIdx.x*32;

    for (int t = tid; t < C*64; t += 256){
        int o = t & 63, c = t >> 6;
        float lo = W[(size_t)o*(2*C) + c];
        Wlo[c*64 + o] = lo;
        Wd [c*64 + o] = W[(size_t)o*(2*C) + C + c] - lo;
    }
    for (int t = tid; t < 32*C; t += 256){
        int p = t / C, c = t % C;
        xS[p*C + c] = xin[((size_t)pt0 + p)*C + c];
    }
    __syncthreads();

    int o0 = (tid & 15)*4;
    int p0 = (tid >> 4)*2, p1 = p0 + 1;

    float aY0[4]={0,0,0,0}, aT0[4]={0,0,0,0};
    float aY1[4]={0,0,0,0}, aT1[4]={0,0,0,0};

#pragma unroll 4
    for (int c = 0; c < C; c++){
        float4 wl = *(const float4*)&Wlo[c*64 + o0];
        float4 wd = *(const float4*)&Wd [c*64 + o0];
        float x0 = xS[p0*C + c];
        float x1 = xS[p1*C + c];
        aY0[0]=fmaf(x0,wl.x,aY0[0]); aY0[1]=fmaf(x0,wl.y,aY0[1]);
        aY0[2]=fmaf(x0,wl.z,aY0[2]); aY0[3]=fmaf(x0,wl.w,aY0[3]);
        aT0[0]=fmaf(x0,wd.x,aT0[0]); aT0[1]=fmaf(x0,wd.y,aT0[1]);
        aT0[2]=fmaf(x0,wd.z,aT0[2]); aT0[3]=fmaf(x0,wd.w,aT0[3]);
        aY1[0]=fmaf(x1,wl.x,aY1[0]); aY1[1]=fmaf(x1,wl.y,aY1[1]);
        aY1[2]=fmaf(x1,wl.z,aY1[2]); aY1[3]=fmaf(x1,wl.w,aY1[3]);
        aT1[0]=fmaf(x1,wd.x,aT1[0]); aT1[1]=fmaf(x1,wd.y,aT1[1]);
        aT1[2]=fmaf(x1,wd.z,aT1[2]); aT1[3]=fmaf(x1,wd.w,aT1[3]);
    }

    float4 gv = *(const float4*)&bng[o0];
    float4 bv = *(const float4*)&bnb[o0];
    float4 mv = *(const float4*)&bnm[o0];
    float4 vv = *(const float4*)&bnv[o0];
    float s[4], bo[4];
    s[0] = gv.x*rsqrtf(vv.x + EPSB); bo[0] = bv.x - mv.x*s[0];
    s[1] = gv.y*rsqrtf(vv.y + EPSB); bo[1] = bv.y - mv.y*s[1];
    s[2] = gv.z*rsqrtf(vv.z + EPSB); bo[2] = bv.z - mv.z*s[2];
    s[3] = gv.w*rsqrtf(vv.w + EPSB); bo[3] = bv.w - mv.w*s[3];

    float4 r;
    r = make_float4(s[0]*aY0[0], s[1]*aY0[1], s[2]*aY0[2], s[3]*aY0[3]);
    *(float4*)&g_Y[((size_t)pt0 + p0)*64 + o0] = r;
    r = make_float4(s[0]*aY1[0], s[1]*aY1[1], s[2]*aY1[2], s[3]*aY1[3]);
    *(float4*)&g_Y[((size_t)pt0 + p1)*64 + o0] = r;
    r = make_float4(fmaf(s[0],aT0[0],bo[0]), fmaf(s[1],aT0[1],bo[1]),
                    fmaf(s[2],aT0[2],bo[2]), fmaf(s[3],aT0[3],bo[3]));
    *(float4*)&g_T[((size_t)pt0 + p0)*64 + o0] = r;
    r = make_float4(fmaf(s[0],aT1[0],bo[0]), fmaf(s[1],aT1[1],bo[1]),
                    fmaf(s[2],aT1[2],bo[2]), fmaf(s[3],aT1[3],bo[3]));
    *(float4*)&g_T[((size_t)pt0 + p1)*64 + o0] = r;
}

// ---------------- edge_conv2: h1=lrelu(Y'[j]+T'[i]) tile -> conv-b -> k-max -
template<int SEL_OUT>
__global__ __launch_bounds__(512) void edge_conv2_kernel(
    const float* __restrict__ Wb,
    const float* __restrict__ bng, const float* __restrict__ bnb,
    const float* __restrict__ bnm, const float* __restrict__ bnv)
{
    float* __restrict__ xout = (SEL_OUT == 1) ? g_x1 : g_x2;

    __shared__ __align__(16) float Ws[64*64];
    __shared__ __align__(16) float As[64*161];
    __shared__ __align__(16) float red[4*8*64];
    __shared__ int idxS[160];

    int tid = threadIdx.x;
    int pt0 = blockIdx.x*8;

    for (int t = tid; t < 4096; t += 512){
        int o = t & 63, c = t >> 6;
        Ws[c*64 + o] = Wb[(size_t)o*64 + c];
    }
    if (tid < 160) idxS[tid] = g_idx[(size_t)pt0*KNN + tid];
    __syncthreads();

    for (int e = tid; e < 160*64; e += 512){
        int r = e >> 6, c = e & 63;
        int p = r / KNN;
        int bb = (pt0 + p) >> 11;
        int j = idxS[r];
        float v = g_Y[((size_t)bb*NN + j)*64 + c] + g_T[((size_t)pt0 + p)*64 + c];
        As[c*161 + r] = lrelu(v);
    }

    int r5 = tid & 31;
    int tn = tid >> 5;
    int o0 = tn*4;

    float s2[4], b2[4];
#pragma unroll
    for (int q = 0; q < 4; q++){
        int o = o0 + q;
        float r = rsqrtf(bnv[o] + EPSB);
        s2[q] = bng[o]*r; b2[q] = bnb[o] - bnm[o]*s2[q];
    }
    __syncthreads();

    float acc[5][4];
#pragma unroll
    for (int i = 0; i < 5; i++)
#pragma unroll
        for (int q = 0; q < 4; q++) acc[i][q] = 0.f;

#pragma unroll 4
    for (int c = 0; c < 64; c++){
        float4 w = *(const float4*)&Ws[c*64 + o0];
        float a0 = As[c*161 + r5*5 + 0];
        float a1 = As[c*161 + r5*5 + 1];
        float a2 = As[c*161 + r5*5 + 2];
        float a3 = As[c*161 + r5*5 + 3];
        float a4 = As[c*161 + r5*5 + 4];
        acc[0][0]=fmaf(a0,w.x,acc[0][0]); acc[0][1]=fmaf(a0,w.y,acc[0][1]);
        acc[0][2]=fmaf(a0,w.z,acc[0][2]); acc[0][3]=fmaf(a0,w.w,acc[0][3]);
        acc[1][0]=fmaf(a1,w.x,acc[1][0]); acc[1][1]=fmaf(a1,w.y,acc[1][1]);
        acc[1][2]=fmaf(a1,w.z,acc[1][2]); acc[1][3]=fmaf(a1,w.w,acc[1][3]);
        acc[2][0]=fmaf(a2,w.x,acc[2][0]); acc[2][1]=fmaf(a2,w.y,acc[2][1]);
        acc[2][2]=fmaf(a2,w.z,acc[2][2]); acc[2][3]=fmaf(a2,w.w,acc[2][3]);
        acc[3][0]=fmaf(a3,w.x,acc[3][0]); acc[3][1]=fmaf(a3,w.y,acc[3][1]);
        acc[3][2]=fmaf(a3,w.z,acc[3][2]); acc[3][3]=fmaf(a3,w.w,acc[3][3]);
        acc[4][0]=fmaf(a4,w.x,acc[4][0]); acc[4][1]=fmaf(a4,w.y,acc[4][1]);
        acc[4][2]=fmaf(a4,w.z,acc[4][2]); acc[4][3]=fmaf(a4,w.w,acc[4][3]);
    }

    int p    = r5 >> 2;
    int part = r5 & 3;
#pragma unroll
    for (int q = 0; q < 4; q++){
        float mx = -CUDART_INF_F;
#pragma unroll
        for (int i = 0; i < 5; i++)
            mx = fmaxf(mx, lrelu(fmaf(acc[i][q], s2[q], b2[q])));
        red[(part*8 + p)*64 + o0 + q] = mx;
    }
    __syncthreads();

    {
        int pp = tid >> 6, oo = tid & 63;
        float m = red[(0*8 + pp)*64 + oo];
        m = fmaxf(m, red[(1*8 + pp)*64 + oo]);
        m = fmaxf(m, red[(2*8 + pp)*64 + oo]);
        m = fmaxf(m, red[(3*8 + pp)*64 + oo]);
        xout[((size_t)pt0 + pp)*64 + oo] = m;
    }
}

// ---------------- edge_max (stage 3): x3 = max_k lrelu(Y'[j]+T'[i]) --------
__global__ __launch_bounds__(256) void edge_max_kernel()
{
    __shared__ int idxS[4*KNN];
    int tid = threadIdx.x;
    int pt0 = blockIdx.x*4;
    if (tid < 4*KNN) idxS[tid] = g_idx[(size_t)pt0*KNN + tid];
    __syncthreads();

    int p = tid >> 6, o = tid & 63;
    int pt = pt0 + p;
    int bb = pt >> 11;
    float tv = g_T[(size_t)pt*64 + o];
    float m = -CUDART_INF_F;
#pragma unroll
    for (int k = 0; k < KNN; k++){
        int j = idxS[p*KNN + k];
        m = fmaxf(m, lrelu(g_Y[((size_t)bb*NN + j)*64 + o] + tv));
    }
    g_x3[(size_t)pt*64 + o] = m;
}

// ---------------- init / final GEMM v2 / outputs ---------------------------
__global__ void init_gmax_kernel(){
    int t = blockIdx.x*256 + threadIdx.x;
    if (t < BB*1024) g_gmax[t] = 0u;
}

__global__ __launch_bounds__(256) void final_kernel(
    const float* __restrict__ W6,
    const float* __restrict__ bn6g, const float* __restrict__ bn6b,
    const float* __restrict__ bn6m, const float* __restrict__ bn6v)
{
    extern __shared__ float dsm[];
    float* Bs = dsm;              // [192*68]
    float* As = dsm + 192*68;     // [192*68]
    __shared__ float ss6[64], sb6[64];
    __shared__ float red[64*16];

    int tid = threadIdx.x;
    int n0 = blockIdx.x*64;
    int bb = blockIdx.y;
    int mc = blockIdx.z;

    if (tid < 64){
        int o = n0 + tid;
        float r = rsqrtf(bn6v[o] + EPSB);
        ss6[tid] = bn6g[o]*r; sb6[tid] = bn6b[o] - bn6m[o]*ss6[tid];
    }

    for (int ch = 0; ch < 3; ch++)
        for (int t = tid; t < 4096; t += 256){
            int nn = t >> 6, c = t & 63;
            Bs[(ch*64 + c)*68 + nn] = W6[(size_t)(n0+nn)*192 + ch*64 + c];
        }
    __syncthreads();

    int tm = tid & 15, tn = tid >> 4;
    float s6[4], b6[4];
#pragma unroll
    for (int q = 0; q < 4; q++){ s6[q] = ss6[tn*4+q]; b6[q] = sb6[tn*4+q]; }

    float vmax[4] = {-CUDART_INF_F, -CUDART_INF_F, -CUDART_INF_F, -CUDART_INF_F};

    for (int mi = mc*8; mi < mc*8 + 8; mi++){
        size_t m1 = (size_t)bb*NN + mi*64;
        __syncthreads();
        {
            for (int t = tid; t < 4096; t += 256){
                int m = t >> 6, c = t & 63;
                As[(0*64 + c)*68 + m] = g_x1[(m1 + m)*64 + c];
            }
            for (int t = tid; t < 4096; t += 256){
                int m = t >> 6, c = t & 63;
                As[(1*64 + c)*68 + m] = g_x2[(m1 + m)*64 + c];
            }
            for (int t = tid; t < 4096; t += 256){
                int m = t >> 6, c = t & 63;
                As[(2*64 + c)*68 + m] = g_x3[(m1 + m)*64 + c];
            }
        }
        __syncthreads();

        float acc[4][4];
#pragma unroll
        for (int i = 0; i < 4; i++)
#pragma unroll
            for (int j = 0; j < 4; j++) acc[i][j] = 0.f;

#pragma unroll 8
        for (int c = 0; c < 192; c++){
            float4 a  = *(const float4*)&As[c*68 + tm*4];
            float4 bv = *(const float4*)&Bs[c*68 + tn*4];
            acc[0][0] = fmaf(a.x,bv.x,acc[0][0]); acc[0][1] = fmaf(a.x,bv.y,acc[0][1]);
            acc[0][2] = fmaf(a.x,bv.z,acc[0][2]); acc[0][3] = fmaf(a.x,bv.w,acc[0][3]);
            acc[1][0] = fmaf(a.y,bv.x,acc[1][0]); acc[1][1] = fmaf(a.y,bv.y,acc[1][1]);
            acc[1][2] = fmaf(a.y,bv.z,acc[1][2]); acc[1][3] = fmaf(a.y,bv.w,acc[1][3]);
            acc[2][0] = fmaf(a.z,bv.x,acc[2][0]); acc[2][1] = fmaf(a.z,bv.y,acc[2][1]);
            acc[2][2] = fmaf(a.z,bv.z,acc[2][2]); acc[2][3] = fmaf(a.z,bv.w,acc[2][3]);
            acc[3][0] = fmaf(a.w,bv.x,acc[3][0]); acc[3][1] = fmaf(a.w,bv.y,acc[3][1]);
            acc[3][2] = fmaf(a.w,bv.z,acc[3][2]); acc[3][3] = fmaf(a.w,bv.w,acc[3][3]);
        }
#pragma unroll
        for (int nq = 0; nq < 4; nq++)
#pragma unroll
            for (int mq = 0; mq < 4; mq++)
                vmax[nq] = fmaxf(vmax[nq], lrelu(fmaf(acc[mq][nq], s6[nq], b6[nq])));
    }

    __syncthreads();
#pragma unroll
    for (int nq = 0; nq < 4; nq++) red[(tn*4+nq)*16 + tm] = vmax[nq];
    __syncthreads();
    if (tid < 64){
        float mx = -CUDART_INF_F;
#pragma unroll
        for (int t = 0; t < 16; t++) mx = fmaxf(mx, red[tid*16 + t]);
        atomicMax(&g_gmax[bb*1024 + n0 + tid], fenc(mx));
    }
}

__global__ void feat_kernel(float* __restrict__ out){
    int t = blockIdx.x*256 + threadIdx.x;
    if (t < BB*1024) out[t] = fdec(g_gmax[t]);
}

// ---------------- x4^T via smem transpose ----------------------------------
__global__ __launch_bounds__(256) void x4t_kernel(float* __restrict__ out)
{
    __shared__ float T[64*65];
    int tid = threadIdx.x;
    int n0 = blockIdx.x*64;
    int bb = blockIdx.y;
    int ch = blockIdx.z;
    const float* src = (ch == 0) ? g_x1 : (ch == 1) ? g_x2 : g_x3;

    for (int t = tid; t < 4096; t += 256){
        int c = t & 63, n = t >> 6;
        T[c*65 + n] = src[((size_t)bb*NN + n0 + n)*64 + c];
    }
    __syncthreads();
    size_t base = (size_t)BB*1024 + (size_t)bb*192*NN + (size_t)ch*64*NN;
    for (int t = tid; t < 4096; t += 256){
        int n = t & 63, c = t >> 6;
        out[base + (size_t)c*NN + n0 + n] = T[c*65 + n];
    }
}

// ---------------- launch ----------------------------------------------------
extern "C" void kernel_launch(void* const* d_in, const int* in_sizes, int n_in,
                              void* d_out, int out_size)
{
    const float* x    = (const float*)d_in[0];
    const float* W1   = (const float*)d_in[1];
    const float* W2   = (const float*)d_in[2];
    const float* W3   = (const float*)d_in[3];
    const float* W4   = (const float*)d_in[4];
    const float* W5   = (const float*)d_in[5];
    const float* W6   = (const float*)d_in[6];
    const float* bng  = (const float*)d_in[7];
    const float* bnb  = (const float*)d_in[8];
    const float* bnm  = (const float*)d_in[9];
    const float* bnv  = (const float*)d_in[10];
    const float* bn6g = (const float*)d_in[11];
    const float* bn6b = (const float*)d_in[12];
    const float* bn6m = (const float*)d_in[13];
    const float* bn6v = (const float*)d_in[14];
    float* out = (float*)d_out;

    cudaFuncSetAttribute(final_kernel,
        cudaFuncAttributeMaxDynamicSharedMemorySize, 2*192*68*4);
    const int FSMEM = 2*192*68*4;

    // Stage 1                                                       (launch idx)
    knn_kernel<<<dim3(BB, NN/256), 256>>>(x, 0);                              // 0
    gemmYT_kernel<3,0><<<NTOT/32, 256>>>(x, W1, bng, bnb, bnm, bnv);          // 1
    edge_conv2_kernel<1><<<NTOT/8, 512>>>(W2, bng+64, bnb+64, bnm+64, bnv+64);// 2

    // Stage 2 — knn1 lands at capture idx 3 (free measurement)
    knn_kernel<<<dim3(BB, NN/256), 256>>>(x, 1);                              // 3
    gemmYT_kernel<64,1><<<NTOT/32, 256>>>(x, W3, bng+2*64, bnb+2*64, bnm+2*64, bnv+2*64); // 4
    edge_conv2_kernel<2><<<NTOT/8, 512>>>(W4, bng+3*64, bnb+3*64, bnm+3*64, bnv+3*64);    // 5

    // Stage 3
    knn_kernel<<<dim3(BB, NN/256), 256>>>(x, 2);                              // 6
    gemmYT_kernel<64,2><<<NTOT/32, 256>>>(x, W5, bng+4*64, bnb+4*64, bnm+4*64, bnv+4*64); // 7
    edge_max_kernel<<<NTOT/4, 256>>>();                                       // 8

    // Final block + global max pool
    init_gmax_kernel<<<32, 256>>>();
    final_kernel<<<dim3(1024/64, BB, 4), 256, FSMEM>>>(W6, bn6g, bn6b, bn6m, bn6v);
    feat_kernel<<<32, 256>>>(out);
    x4t_kernel<<<dim3(NN/64, BB, 3), 256>>>(out);
}